// round 2
// baseline (speedup 1.0000x reference)
#include <cuda_runtime.h>
#include <cuda_bf16.h>
#include <cstdint>

// LightGCN reference collapses: deg accumulates only on item (col) nodes, so
// dinv[row]==0 for every edge (rows are users) => norm==0 => all propagation
// layers are exactly zero. Output is just:
//   user_emb = l2norm(user_emb_weight)
//   item_emb = l2norm(item_audio + 0.5*(artist_emb[aid] + album_emb[alid]))
//   align_loss = 0.0
// (l2norm(l2norm(v)/4) == l2norm(v) by positive-scale invariance.)

#define NUM_USERS 500000
#define NUM_ITEMS 200000
#define N_ROWS    (NUM_USERS + NUM_ITEMS)
#define EMBED_DIM 128
#define VEC_PER_ROW 32   // 128 floats = 32 float4
#define EPS 1e-12f

__global__ __launch_bounds__(256)
void lightgcn_fused_kernel(const float4* __restrict__ user_w,
                           const float4* __restrict__ audio,
                           const float4* __restrict__ artist,
                           const float4* __restrict__ album,
                           const int*    __restrict__ artist_ids,
                           const int*    __restrict__ album_ids,
                           float4* __restrict__ out,
                           float*  __restrict__ out_scalar,
                           int write_scalar)
{
    const int warp = (blockIdx.x * blockDim.x + threadIdx.x) >> 5;
    const int lane = threadIdx.x & 31;

    if (warp == 0 && lane == 0 && write_scalar) {
        out_scalar[0] = 0.0f;   // align_loss
    }
    if (warp >= N_ROWS) return;

    float4 v;
    if (warp < NUM_USERS) {
        v = user_w[(size_t)warp * VEC_PER_ROW + lane];
    } else {
        const int i = warp - NUM_USERS;
        // broadcast the two indices from lane 0 (single LDG per warp)
        int aid, alid;
        if (lane == 0) { aid = artist_ids[i]; alid = album_ids[i]; }
        aid  = __shfl_sync(0xffffffffu, aid,  0);
        alid = __shfl_sync(0xffffffffu, alid, 0);

        const float4 a  = audio [(size_t)i    * VEC_PER_ROW + lane];
        const float4 ar = artist[(size_t)aid  * VEC_PER_ROW + lane];
        const float4 al = album [(size_t)alid * VEC_PER_ROW + lane];
        v.x = fmaf(0.5f, ar.x + al.x, a.x);
        v.y = fmaf(0.5f, ar.y + al.y, a.y);
        v.z = fmaf(0.5f, ar.z + al.z, a.z);
        v.w = fmaf(0.5f, ar.w + al.w, a.w);
    }

    // sum of squares across the row (warp-wide)
    float ss = v.x * v.x + v.y * v.y + v.z * v.z + v.w * v.w;
    #pragma unroll
    for (int o = 16; o > 0; o >>= 1)
        ss += __shfl_xor_sync(0xffffffffu, ss, o);

    const float inv = 1.0f / fmaxf(sqrtf(ss), EPS);
    v.x *= inv; v.y *= inv; v.z *= inv; v.w *= inv;

    out[(size_t)warp * VEC_PER_ROW + lane] = v;
}

extern "C" void kernel_launch(void* const* d_in, const int* in_sizes, int n_in,
                              void* d_out, int out_size)
{
    // metadata order:
    // 0: user_emb_weight  (500000*128 f32)
    // 1: item_audio_emb   (200000*128 f32)
    // 2: artist_emb_weight(50000*128 f32)
    // 3: album_emb_weight (100000*128 f32)
    // 4: w1  5: b1  6: w2  7: b2  (unused — propagation is zero)
    // 8: edge_features (unused)
    // 9: artist_ids (200000 i32)
    // 10: album_ids (200000 i32)
    // 11: edge_index (unused)
    const float4* user_w = (const float4*)d_in[0];
    const float4* audio  = (const float4*)d_in[1];
    const float4* artist = (const float4*)d_in[2];
    const float4* album  = (const float4*)d_in[3];
    const int* artist_ids = (const int*)d_in[9];
    const int* album_ids  = (const int*)d_in[10];

    float* out_f = (float*)d_out;
    const long long emb_elems = (long long)N_ROWS * EMBED_DIM;
    const int write_scalar = (out_size > emb_elems) ? 1 : 0;
    float* out_scalar = out_f + emb_elems;

    const int threads = 256;                 // 8 warps/block, 1 warp per row
    const int rows_per_block = threads / 32;
    const int blocks = (N_ROWS + rows_per_block - 1) / rows_per_block;

    lightgcn_fused_kernel<<<blocks, threads>>>(
        user_w, audio, artist, album, artist_ids, album_ids,
        (float4*)d_out, out_scalar, write_scalar);
}

// round 3
// speedup vs baseline: 1.0277x; 1.0277x over previous
#include <cuda_runtime.h>
#include <cuda_bf16.h>
#include <cstdint>

// LightGCN reference collapses: deg accumulates only on item (col) nodes, so
// dinv[row]==0 for every edge (rows are users) => norm==0 => propagation
// layers are exactly zero. Output:
//   user_emb = l2norm(user_emb_weight)
//   item_emb = l2norm(item_audio + 0.5*(artist_emb[aid] + album_emb[alid]))
//   align_loss = 0.0
//
// R2: cache-policy split — streaming reads/writes use evict-first (.cs) so the
// 76.8MB artist/album gather tables (with 2-4x reuse) stay L2-resident instead
// of being thrashed by ~718MB of single-use streaming traffic.

#define NUM_USERS 500000
#define NUM_ITEMS 200000
#define N_ROWS    (NUM_USERS + NUM_ITEMS)
#define EMBED_DIM 128
#define VEC_PER_ROW 32   // 128 floats = 32 float4

__global__ __launch_bounds__(256)
void lightgcn_fused_kernel(const float4* __restrict__ user_w,
                           const float4* __restrict__ audio,
                           const float4* __restrict__ artist,
                           const float4* __restrict__ album,
                           const int*    __restrict__ artist_ids,
                           const int*    __restrict__ album_ids,
                           float4* __restrict__ out,
                           float*  __restrict__ out_scalar,
                           int write_scalar)
{
    const int warp = (blockIdx.x * blockDim.x + threadIdx.x) >> 5;
    const int lane = threadIdx.x & 31;

    if (warp == 0 && lane == 0 && write_scalar) {
        out_scalar[0] = 0.0f;   // align_loss
    }
    if (warp >= N_ROWS) return;

    float4 v;
    if (warp < NUM_USERS) {
        // pure stream: evict-first, no reuse
        v = __ldcs(&user_w[(size_t)warp * VEC_PER_ROW + lane]);
    } else {
        const int i = warp - NUM_USERS;
        // all lanes load the same index word — HW broadcasts, one L1 request,
        // no shfl on the critical path. ids are tiny (800KB), keep cached.
        const int aid  = __ldg(&artist_ids[i]);
        const int alid = __ldg(&album_ids[i]);

        // audio is streaming (single use); tables are gathered with reuse ->
        // default (evict-normal) caching so they stay in L2.
        const float4 a  = __ldcs(&audio[(size_t)i * VEC_PER_ROW + lane]);
        const float4 ar = __ldg (&artist[(size_t)aid  * VEC_PER_ROW + lane]);
        const float4 al = __ldg (&album [(size_t)alid * VEC_PER_ROW + lane]);
        v.x = fmaf(0.5f, ar.x + al.x, a.x);
        v.y = fmaf(0.5f, ar.y + al.y, a.y);
        v.z = fmaf(0.5f, ar.z + al.z, a.z);
        v.w = fmaf(0.5f, ar.w + al.w, a.w);
    }

    // sum of squares across the row (warp-wide)
    float ss = fmaf(v.x, v.x, fmaf(v.y, v.y, fmaf(v.z, v.z, v.w * v.w)));
    #pragma unroll
    for (int o = 16; o > 0; o >>= 1)
        ss += __shfl_xor_sync(0xffffffffu, ss, o);

    // rows have norm ~1 (>> eps), rsqrtf is safe at 1e-3 tolerance
    const float inv = rsqrtf(ss);
    v.x *= inv; v.y *= inv; v.z *= inv; v.w *= inv;

    // output is write-once: evict-first
    __stcs(&out[(size_t)warp * VEC_PER_ROW + lane], v);
}

extern "C" void kernel_launch(void* const* d_in, const int* in_sizes, int n_in,
                              void* d_out, int out_size)
{
    // metadata order:
    // 0: user_emb_weight  (500000*128 f32)
    // 1: item_audio_emb   (200000*128 f32)
    // 2: artist_emb_weight(50000*128 f32)
    // 3: album_emb_weight (100000*128 f32)
    // 4: w1  5: b1  6: w2  7: b2  (unused — propagation is zero)
    // 8: edge_features (unused)
    // 9: artist_ids (200000 i32)
    // 10: album_ids (200000 i32)
    // 11: edge_index (unused)
    const float4* user_w = (const float4*)d_in[0];
    const float4* audio  = (const float4*)d_in[1];
    const float4* artist = (const float4*)d_in[2];
    const float4* album  = (const float4*)d_in[3];
    const int* artist_ids = (const int*)d_in[9];
    const int* album_ids  = (const int*)d_in[10];

    float* out_f = (float*)d_out;
    const long long emb_elems = (long long)N_ROWS * EMBED_DIM;
    const int write_scalar = (out_size > emb_elems) ? 1 : 0;
    float* out_scalar = out_f + emb_elems;

    const int threads = 256;                 // 8 warps/block, 1 warp per row
    const int rows_per_block = threads / 32;
    const int blocks = (N_ROWS + rows_per_block - 1) / rows_per_block;

    lightgcn_fused_kernel<<<blocks, threads>>>(
        user_w, audio, artist, album, artist_ids, album_ids,
        (float4*)d_out, out_scalar, write_scalar);
}

// round 4
// speedup vs baseline: 1.1186x; 1.0884x over previous
#include <cuda_runtime.h>
#include <cuda_bf16.h>
#include <cstdint>

// LightGCN reference collapses: deg accumulates only on item (col) nodes, so
// dinv[row]==0 for every edge (rows are users) => norm==0 => propagation
// layers are exactly zero. Output:
//   user_emb = l2norm(user_emb_weight)
//   item_emb = l2norm(item_audio + 0.5*(artist_emb[aid] + album_emb[alid]))
//   align_loss = 0.0
//
// R3: 2 rows per warp — batch both rows' loads before reducing (MLP_p1 x2),
// interleave two independent shfl-reduction chains (ILP-2 on the 5x26cyc
// butterfly), amortize scheduling. Keeps R2's cache-policy split.

#define NUM_USERS 500000
#define NUM_ITEMS 200000
#define N_ROWS    (NUM_USERS + NUM_ITEMS)   // 700000, even; boundary 500000 even
#define EMBED_DIM 128
#define VEC_PER_ROW 32   // 128 floats = 32 float4

__device__ __forceinline__ float4 load_row(int row, int lane,
                                           const float4* __restrict__ user_w,
                                           const float4* __restrict__ audio,
                                           const float4* __restrict__ artist,
                                           const float4* __restrict__ album,
                                           const int*    __restrict__ artist_ids,
                                           const int*    __restrict__ album_ids)
{
    if (row < NUM_USERS) {
        return __ldcs(&user_w[(size_t)row * VEC_PER_ROW + lane]);
    }
    const int i = row - NUM_USERS;
    const int aid  = __ldg(&artist_ids[i]);   // broadcast load, tables tiny
    const int alid = __ldg(&album_ids[i]);
    const float4 a  = __ldcs(&audio[(size_t)i * VEC_PER_ROW + lane]);
    const float4 ar = __ldg (&artist[(size_t)aid  * VEC_PER_ROW + lane]);
    const float4 al = __ldg (&album [(size_t)alid * VEC_PER_ROW + lane]);
    float4 v;
    v.x = fmaf(0.5f, ar.x + al.x, a.x);
    v.y = fmaf(0.5f, ar.y + al.y, a.y);
    v.z = fmaf(0.5f, ar.z + al.z, a.z);
    v.w = fmaf(0.5f, ar.w + al.w, a.w);
    return v;
}

__global__ __launch_bounds__(256)
void lightgcn_fused_kernel(const float4* __restrict__ user_w,
                           const float4* __restrict__ audio,
                           const float4* __restrict__ artist,
                           const float4* __restrict__ album,
                           const int*    __restrict__ artist_ids,
                           const int*    __restrict__ album_ids,
                           float4* __restrict__ out,
                           float*  __restrict__ out_scalar,
                           int write_scalar)
{
    const int warp = (blockIdx.x * blockDim.x + threadIdx.x) >> 5;
    const int lane = threadIdx.x & 31;

    if (warp == 0 && lane == 0 && write_scalar) {
        out_scalar[0] = 0.0f;   // align_loss
    }

    const int row0 = warp * 2;
    if (row0 >= N_ROWS) return;
    const int row1 = row0 + 1;   // N_ROWS even -> always valid

    // Issue all loads for both rows before any reduction (deep MLP).
    float4 v0 = load_row(row0, lane, user_w, audio, artist, album,
                         artist_ids, album_ids);
    float4 v1 = load_row(row1, lane, user_w, audio, artist, album,
                         artist_ids, album_ids);

    // Two independent butterfly reductions, interleaved for ILP.
    float s0 = fmaf(v0.x, v0.x, fmaf(v0.y, v0.y, fmaf(v0.z, v0.z, v0.w * v0.w)));
    float s1 = fmaf(v1.x, v1.x, fmaf(v1.y, v1.y, fmaf(v1.z, v1.z, v1.w * v1.w)));
    #pragma unroll
    for (int o = 16; o > 0; o >>= 1) {
        s0 += __shfl_xor_sync(0xffffffffu, s0, o);
        s1 += __shfl_xor_sync(0xffffffffu, s1, o);
    }

    const float inv0 = rsqrtf(s0);   // row norms ~1 >> eps
    const float inv1 = rsqrtf(s1);
    v0.x *= inv0; v0.y *= inv0; v0.z *= inv0; v0.w *= inv0;
    v1.x *= inv1; v1.y *= inv1; v1.z *= inv1; v1.w *= inv1;

    __stcs(&out[(size_t)row0 * VEC_PER_ROW + lane], v0);
    __stcs(&out[(size_t)row1 * VEC_PER_ROW + lane], v1);
}

extern "C" void kernel_launch(void* const* d_in, const int* in_sizes, int n_in,
                              void* d_out, int out_size)
{
    // metadata order:
    // 0: user_emb_weight  (500000*128 f32)
    // 1: item_audio_emb   (200000*128 f32)
    // 2: artist_emb_weight(50000*128 f32)
    // 3: album_emb_weight (100000*128 f32)
    // 4: w1  5: b1  6: w2  7: b2  (unused — propagation is zero)
    // 8: edge_features (unused)
    // 9: artist_ids (200000 i32)
    // 10: album_ids (200000 i32)
    // 11: edge_index (unused)
    const float4* user_w = (const float4*)d_in[0];
    const float4* audio  = (const float4*)d_in[1];
    const float4* artist = (const float4*)d_in[2];
    const float4* album  = (const float4*)d_in[3];
    const int* artist_ids = (const int*)d_in[9];
    const int* album_ids  = (const int*)d_in[10];

    float* out_f = (float*)d_out;
    const long long emb_elems = (long long)N_ROWS * EMBED_DIM;
    const int write_scalar = (out_size > emb_elems) ? 1 : 0;
    float* out_scalar = out_f + emb_elems;

    const int threads = 256;                  // 8 warps/block, 2 rows per warp
    const int rows_per_block = (threads / 32) * 2;
    const int blocks = (N_ROWS + rows_per_block - 1) / rows_per_block;

    lightgcn_fused_kernel<<<blocks, threads>>>(
        user_w, audio, artist, album, artist_ids, album_ids,
        (float4*)d_out, out_scalar, write_scalar);
}